// round 9
// baseline (speedup 1.0000x reference)
#include <cuda_runtime.h>
#include <cstdint>

// Yolo_Loss: S=56, B=5, C=20, N=128.
// predicts: [N,S,S,B,25] f32, targets: [N,S,S,25] f32, anchors: [5,2] f32.
// R2 structure (non-persistent grid 3136, one-shot TMA bulk copy per CTA,
// fire-and-forget RED per CTA into g_sum) + PDL finisher kernel
// (programmatic stream serialization hides the second node's launch gap).
// No gpu-scope fences anywhere (they drain in-flight TMA on sm_103a: R5/R6).

#define S_DIM 56
#define N_IMG 128
#define B_BOX 5
#define C_CLS 20
#define CVEC  25                       // C+5
#define CELLS (N_IMG * S_DIM * S_DIM)  // 401408
#define CPB   128                      // cells per block (== threads per block)
#define GRID  (CELLS / CPB)            // 3136
#define PW    (CPB * CVEC * B_BOX)     // 16000 floats of predicts per block
#define TW    (CPB * CVEC)             // 3200 floats of targets per block
#define PBYTES (PW * 4)                // 64000 B
#define TBYTES (TW * 4)                // 12800 B
#define SMEM_BYTES (PBYTES + TBYTES)   // 76800 B dynamic smem

__device__ float g_sum = 0.0f;

__device__ __forceinline__ float sigmoid_f(float x) {
    // sigmoid(x) = 0.5 * tanh(0.5x) + 0.5  (1 MUFU)
    float t;
    asm("tanh.approx.f32 %0, %1;" : "=f"(t) : "f"(x * 0.5f));
    return fmaf(0.5f, t, 0.5f);
}

__device__ __forceinline__ uint32_t smem_u32(const void* p) {
    return (uint32_t)__cvta_generic_to_shared(p);
}

__global__ __launch_bounds__(CPB) void yolo_loss_kernel(
    const float* __restrict__ gp,   // predicts
    const float* __restrict__ gt,   // targets
    const float* __restrict__ ga,   // anchors (10 floats)
    float* __restrict__ out)
{
    extern __shared__ __align__(128) float sm[];
    float* sp = sm;        // [PW] predicts for this block's cells
    float* st = sm + PW;   // [TW] targets  for this block's cells
    __shared__ __align__(8) unsigned long long mbar;
    __shared__ float wsum[CPB / 32];

    const int tid = threadIdx.x;
    const uint32_t mbar_a = smem_u32(&mbar);

    if (tid == 0) {
        asm volatile("mbarrier.init.shared.b64 [%0], 1;" :: "r"(mbar_a) : "memory");
    }
    __syncthreads();

    // ---- One-shot TMA bulk copy of the whole tile (max MLP, zero reg pressure) ----
    if (tid == 0) {
        asm volatile("mbarrier.arrive.expect_tx.shared.b64 _, [%0], %1;"
                     :: "r"(mbar_a), "r"((uint32_t)SMEM_BYTES) : "memory");
        const char* gpp = (const char*)(gp + (size_t)blockIdx.x * PW);
        const char* gtp = (const char*)(gt + (size_t)blockIdx.x * TW);
        asm volatile(
            "cp.async.bulk.shared::cta.global.mbarrier::complete_tx::bytes [%0], [%1], %2, [%3];"
            :: "r"(smem_u32(sp)), "l"(gpp), "r"((uint32_t)PBYTES), "r"(mbar_a) : "memory");
        asm volatile(
            "cp.async.bulk.shared::cta.global.mbarrier::complete_tx::bytes [%0], [%1], %2, [%3];"
            :: "r"(smem_u32(st)), "l"(gtp), "r"((uint32_t)TBYTES), "r"(mbar_a) : "memory");
    }

    // ---- Wait for the bulk copy (acquire orders subsequent ld.shared) ----
    {
        uint32_t done;
        asm volatile(
            "{\n\t.reg .pred p;\n\t"
            "mbarrier.try_wait.parity.acquire.cta.shared::cta.b64 p, [%1], 0;\n\t"
            "selp.b32 %0, 1, 0, p;\n\t}"
            : "=r"(done) : "r"(mbar_a) : "memory");
        if (!done) {
            asm volatile(
                "{\n\t.reg .pred P1;\n\t"
                "WAIT_LOOP_%=:\n\t"
                "mbarrier.try_wait.parity.acquire.cta.shared::cta.b64 P1, [%0], 0, 0x989680;\n\t"
                "@P1 bra.uni WAIT_DONE_%=;\n\t"
                "bra.uni WAIT_LOOP_%=;\n\t"
                "WAIT_DONE_%=:\n\t}"
                :: "r"(mbar_a) : "memory");
        }
    }

    // ---- Per-cell compute. smem strides 125 / 25 words: odd -> bank-conflict-free ----
    const float* pc = sp + tid * (CVEC * B_BOX);
    const float* tc = st + tid * CVEC;

    const float e   = tc[C_CLS];
    const float tcx = tc[C_CLS + 1], tcy = tc[C_CLS + 2];
    const float tw  = tc[C_CLS + 3], th  = tc[C_CLS + 4];
    const float tx1 = tcx - 0.5f * tw, ty1 = tcy - 0.5f * th;
    const float tx2 = tcx + 0.5f * tw, ty2 = tcy + 0.5f * th;
    const float area_t = tw * th;

    // Argmax over IoU via cross-multiplication (dens > 0); init guarantees b=0 wins first.
    float bnum = -1.0f, bden = 1.0f;
    int   bidx = 0;
    float bsx = 0.f, bsy = 0.f, bw = 0.f, bh = 0.f;

#pragma unroll
    for (int b = 0; b < B_BOX; ++b) {
        const float* pb = pc + b * CVEC;
        const float sx = sigmoid_f(pb[C_CLS + 1]);
        const float sy = sigmoid_f(pb[C_CLS + 2]);
        const float w  = __expf(pb[C_CLS + 3]) * __ldg(ga + 2 * b);
        const float h  = __expf(pb[C_CLS + 4]) * __ldg(ga + 2 * b + 1);

        const float x1 = sx - 0.5f * w, y1 = sy - 0.5f * h;
        const float x2 = sx + 0.5f * w, y2 = sy + 0.5f * h;
        const float lx = fmaxf(x1, tx1), ly = fmaxf(y1, ty1);
        const float rx = fminf(x2, tx2), ry = fminf(y2, ty2);
        const float wi = fmaxf(rx - lx, 0.0f);
        const float hi = fmaxf(ry - ly, 0.0f);
        const float inter = wi * hi;
        const float den   = fmaf(w, h, area_t) - inter;  // area_p + area_t - inter

        // iou_b > iou_best  <=>  inter*bden > bnum*den   (strict > == first-max argmax)
        if (inter * bden > bnum * den) {
            bidx = b; bnum = inter; bden = den;
            bsx = sx; bsy = sy; bw = w; bh = h;
        }
    }

    const float e2 = e * e;

    // loss_xcyc
    const float dx = bsx - tcx, dy = bsy - tcy;
    float loss = e2 * (dx * dx + dy * dy);

    // loss_wh: sign(w)*sqrt(|w|+1e-6)
    const float pw = (bw > 0.f) ? sqrtf(bw + 1e-6f)
                                : ((bw < 0.f) ? -sqrtf(-bw + 1e-6f) : 0.f);
    const float ph = (bh > 0.f) ? sqrtf(bh + 1e-6f)
                                : ((bh < 0.f) ? -sqrtf(-bh + 1e-6f) : 0.f);
    const float dw = pw - tw, dh = ph - th;
    loss += e2 * (dw * dw + dh * dh);

    // loss_cls (class 0 of best box scaled by best_idx)
    const float* pbest = pc + bidx * CVEC;
    const float fbidx = (float)bidx;
    float cls = 0.0f;
#pragma unroll
    for (int c = 0; c < C_CLS; ++c) {
        float pv = pbest[c];
        if (c == 0) pv *= fbidx;
        const float d = pv - tc[c];
        cls = fmaf(d, d, cls);
    }
    loss += e2 * cls;

    // loss_obj + loss_noobj: [e^2 + (1-e)^2] * (pobj - e)^2
    const float dobj   = pbest[C_CLS] - e;
    const float one_me = 1.0f - e;
    loss += (e2 + one_me * one_me) * dobj * dobj;

    // ---- Reduction: warp shuffle -> block -> fire-and-forget RED (return unused) ----
#pragma unroll
    for (int o = 16; o; o >>= 1)
        loss += __shfl_xor_sync(0xffffffffu, loss, o);

    if ((tid & 31) == 0) wsum[tid >> 5] = loss;
    __syncthreads();
    if (tid == 0) {
        float s = 0.0f;
#pragma unroll
        for (int i = 0; i < CPB / 32; ++i) s += wsum[i];
        atomicAdd(&g_sum, s);   // return value unused -> ptxas emits RED (no wait)
    }
}

// PDL finisher: launch work is prefetched; starts the moment the primary grid
// completes. griddepcontrol.wait makes all prior RED results visible.
__global__ void yolo_finish(float* __restrict__ out) {
    asm volatile("griddepcontrol.wait;" ::: "memory");
    *out  = g_sum;
    g_sum = 0.0f;   // restore for the next graph replay
}

extern "C" void kernel_launch(void* const* d_in, const int* in_sizes, int n_in,
                              void* d_out, int out_size)
{
    const float* p = (const float*)d_in[0];
    const float* t = (const float*)d_in[1];
    const float* a = (const float*)d_in[2];
    float* out = (float*)d_out;

    cudaFuncSetAttribute(yolo_loss_kernel,
                         cudaFuncAttributeMaxDynamicSharedMemorySize, SMEM_BYTES);

    yolo_loss_kernel<<<GRID, CPB, SMEM_BYTES>>>(p, t, a, out);

    cudaLaunchConfig_t cfg = {};
    cfg.gridDim  = dim3(1, 1, 1);
    cfg.blockDim = dim3(1, 1, 1);
    cudaLaunchAttribute at[1];
    at[0].id = cudaLaunchAttributeProgrammaticStreamSerialization;
    at[0].val.programmaticStreamSerializationAllowed = 1;
    cfg.attrs = at;
    cfg.numAttrs = 1;
    cudaLaunchKernelEx(&cfg, yolo_finish, out);
}

// round 10
// speedup vs baseline: 1.0062x; 1.0062x over previous
#include <cuda_runtime.h>
#include <cstdint>

// Yolo_Loss: S=56, B=5, C=20, N=128.
// predicts: [N,S,S,B,25] f32, targets: [N,S,S,25] f32, anchors: [5,2] f32.
// Non-persistent churn grid (proven best R2), but 112-cell tiles (67.2KB smem)
// so THREE CTAs fit per SM -> a TMA bulk copy is almost always in flight while
// other resident CTAs compute. Fire-and-forget RED per CTA + PDL finisher.
// No gpu-scope fences anywhere (they drain in-flight TMA on sm_103a: R5/R6).

#define S_DIM 56
#define N_IMG 128
#define B_BOX 5
#define C_CLS 20
#define CVEC  25                       // C+5
#define CELLS (N_IMG * S_DIM * S_DIM)  // 401408
#define TILE_CELLS 112                 // cells per block
#define CPB   128                      // threads per block (16 idle in compute)
#define GRID  (CELLS / TILE_CELLS)     // 3584 (exact)
#define PW    (TILE_CELLS * CVEC * B_BOX)  // 14000 floats of predicts per block
#define TW    (TILE_CELLS * CVEC)          //  2800 floats of targets per block
#define PBYTES (PW * 4)                // 56000 B (16B-multiple)
#define TBYTES (TW * 4)                // 11200 B (16B-multiple)
#define SMEM_BYTES (PBYTES + TBYTES)   // 67200 B dynamic smem -> 3 CTAs/SM

__device__ float g_sum = 0.0f;

__device__ __forceinline__ float sigmoid_f(float x) {
    // sigmoid(x) = 0.5 * tanh(0.5x) + 0.5  (1 MUFU)
    float t;
    asm("tanh.approx.f32 %0, %1;" : "=f"(t) : "f"(x * 0.5f));
    return fmaf(0.5f, t, 0.5f);
}

__device__ __forceinline__ uint32_t smem_u32(const void* p) {
    return (uint32_t)__cvta_generic_to_shared(p);
}

__global__ __launch_bounds__(CPB) void yolo_loss_kernel(
    const float* __restrict__ gp,   // predicts
    const float* __restrict__ gt,   // targets
    const float* __restrict__ ga,   // anchors (10 floats)
    float* __restrict__ out)
{
    extern __shared__ __align__(128) float sm[];
    float* sp = sm;        // [PW] predicts for this block's cells
    float* st = sm + PW;   // [TW] targets  for this block's cells
    __shared__ __align__(8) unsigned long long mbar;
    __shared__ float wsum[CPB / 32];

    const int tid = threadIdx.x;
    const uint32_t mbar_a = smem_u32(&mbar);

    if (tid == 0) {
        asm volatile("mbarrier.init.shared.b64 [%0], 1;" :: "r"(mbar_a) : "memory");
    }
    __syncthreads();

    // ---- One-shot TMA bulk copy of the whole tile ----
    if (tid == 0) {
        asm volatile("mbarrier.arrive.expect_tx.shared.b64 _, [%0], %1;"
                     :: "r"(mbar_a), "r"((uint32_t)SMEM_BYTES) : "memory");
        const char* gpp = (const char*)(gp + (size_t)blockIdx.x * PW);
        const char* gtp = (const char*)(gt + (size_t)blockIdx.x * TW);
        asm volatile(
            "cp.async.bulk.shared::cta.global.mbarrier::complete_tx::bytes [%0], [%1], %2, [%3];"
            :: "r"(smem_u32(sp)), "l"(gpp), "r"((uint32_t)PBYTES), "r"(mbar_a) : "memory");
        asm volatile(
            "cp.async.bulk.shared::cta.global.mbarrier::complete_tx::bytes [%0], [%1], %2, [%3];"
            :: "r"(smem_u32(st)), "l"(gtp), "r"((uint32_t)TBYTES), "r"(mbar_a) : "memory");
    }

    // ---- Wait for the bulk copy (acquire orders subsequent ld.shared) ----
    {
        uint32_t done;
        asm volatile(
            "{\n\t.reg .pred p;\n\t"
            "mbarrier.try_wait.parity.acquire.cta.shared::cta.b64 p, [%1], 0;\n\t"
            "selp.b32 %0, 1, 0, p;\n\t}"
            : "=r"(done) : "r"(mbar_a) : "memory");
        if (!done) {
            asm volatile(
                "{\n\t.reg .pred P1;\n\t"
                "WAIT_LOOP_%=:\n\t"
                "mbarrier.try_wait.parity.acquire.cta.shared::cta.b64 P1, [%0], 0, 0x989680;\n\t"
                "@P1 bra.uni WAIT_DONE_%=;\n\t"
                "bra.uni WAIT_LOOP_%=;\n\t"
                "WAIT_DONE_%=:\n\t}"
                :: "r"(mbar_a) : "memory");
        }
    }

    float loss = 0.0f;

    if (tid < TILE_CELLS) {
        // ---- Per-cell compute. smem strides 125 / 25 words: odd -> conflict-free ----
        const float* pc = sp + tid * (CVEC * B_BOX);
        const float* tc = st + tid * CVEC;

        const float e   = tc[C_CLS];
        const float tcx = tc[C_CLS + 1], tcy = tc[C_CLS + 2];
        const float tw  = tc[C_CLS + 3], th  = tc[C_CLS + 4];
        const float tx1 = tcx - 0.5f * tw, ty1 = tcy - 0.5f * th;
        const float tx2 = tcx + 0.5f * tw, ty2 = tcy + 0.5f * th;
        const float area_t = tw * th;

        // Argmax over IoU via cross-multiplication (dens > 0); init -> b=0 wins first.
        float bnum = -1.0f, bden = 1.0f;
        int   bidx = 0;
        float bsx = 0.f, bsy = 0.f, bw = 0.f, bh = 0.f;

#pragma unroll
        for (int b = 0; b < B_BOX; ++b) {
            const float* pb = pc + b * CVEC;
            const float sx = sigmoid_f(pb[C_CLS + 1]);
            const float sy = sigmoid_f(pb[C_CLS + 2]);
            const float w  = __expf(pb[C_CLS + 3]) * __ldg(ga + 2 * b);
            const float h  = __expf(pb[C_CLS + 4]) * __ldg(ga + 2 * b + 1);

            const float x1 = sx - 0.5f * w, y1 = sy - 0.5f * h;
            const float x2 = sx + 0.5f * w, y2 = sy + 0.5f * h;
            const float lx = fmaxf(x1, tx1), ly = fmaxf(y1, ty1);
            const float rx = fminf(x2, tx2), ry = fminf(y2, ty2);
            const float wi = fmaxf(rx - lx, 0.0f);
            const float hi = fmaxf(ry - ly, 0.0f);
            const float inter = wi * hi;
            const float den   = fmaf(w, h, area_t) - inter;  // area_p + area_t - inter

            // iou_b > iou_best  <=>  inter*bden > bnum*den  (strict > == first-max)
            if (inter * bden > bnum * den) {
                bidx = b; bnum = inter; bden = den;
                bsx = sx; bsy = sy; bw = w; bh = h;
            }
        }

        const float e2 = e * e;

        // loss_xcyc
        const float dx = bsx - tcx, dy = bsy - tcy;
        loss = e2 * (dx * dx + dy * dy);

        // loss_wh: sign(w)*sqrt(|w|+1e-6)
        const float pw = (bw > 0.f) ? sqrtf(bw + 1e-6f)
                                    : ((bw < 0.f) ? -sqrtf(-bw + 1e-6f) : 0.f);
        const float ph = (bh > 0.f) ? sqrtf(bh + 1e-6f)
                                    : ((bh < 0.f) ? -sqrtf(-bh + 1e-6f) : 0.f);
        const float dw = pw - tw, dh = ph - th;
        loss += e2 * (dw * dw + dh * dh);

        // loss_cls (class 0 of best box scaled by best_idx)
        const float* pbest = pc + bidx * CVEC;
        const float fbidx = (float)bidx;
        float cls = 0.0f;
#pragma unroll
        for (int c = 0; c < C_CLS; ++c) {
            float pv = pbest[c];
            if (c == 0) pv *= fbidx;
            const float d = pv - tc[c];
            cls = fmaf(d, d, cls);
        }
        loss += e2 * cls;

        // loss_obj + loss_noobj: [e^2 + (1-e)^2] * (pobj - e)^2
        const float dobj   = pbest[C_CLS] - e;
        const float one_me = 1.0f - e;
        loss += (e2 + one_me * one_me) * dobj * dobj;
    }

    // ---- Reduction: warp shuffle -> block -> fire-and-forget RED (return unused) ----
#pragma unroll
    for (int o = 16; o; o >>= 1)
        loss += __shfl_xor_sync(0xffffffffu, loss, o);

    if ((tid & 31) == 0) wsum[tid >> 5] = loss;
    __syncthreads();
    if (tid == 0) {
        float s = 0.0f;
#pragma unroll
        for (int i = 0; i < CPB / 32; ++i) s += wsum[i];
        atomicAdd(&g_sum, s);   // return value unused -> ptxas emits RED (no wait)
    }
}

// PDL finisher: launch prefetched; griddepcontrol.wait resolves at primary grid
// completion, making all RED results visible.
__global__ void yolo_finish(float* __restrict__ out) {
    asm volatile("griddepcontrol.wait;" ::: "memory");
    *out  = g_sum;
    g_sum = 0.0f;   // restore for the next graph replay
}

extern "C" void kernel_launch(void* const* d_in, const int* in_sizes, int n_in,
                              void* d_out, int out_size)
{
    const float* p = (const float*)d_in[0];
    const float* t = (const float*)d_in[1];
    const float* a = (const float*)d_in[2];
    float* out = (float*)d_out;

    cudaFuncSetAttribute(yolo_loss_kernel,
                         cudaFuncAttributeMaxDynamicSharedMemorySize, SMEM_BYTES);

    yolo_loss_kernel<<<GRID, CPB, SMEM_BYTES>>>(p, t, a, out);

    cudaLaunchConfig_t cfg = {};
    cfg.gridDim  = dim3(1, 1, 1);
    cfg.blockDim = dim3(1, 1, 1);
    cudaLaunchAttribute at[1];
    at[0].id = cudaLaunchAttributeProgrammaticStreamSerialization;
    at[0].val.programmaticStreamSerializationAllowed = 1;
    cfg.attrs = at;
    cfg.numAttrs = 1;
    cudaLaunchKernelEx(&cfg, yolo_finish, out);
}

// round 11
// speedup vs baseline: 1.0069x; 1.0008x over previous
#include <cuda_runtime.h>
#include <cstdint>

// Yolo_Loss: S=56, B=5, C=20, N=128.
// predicts: [N,S,S,B,25] f32, targets: [N,S,S,25] f32, anchors: [5,2] f32.
// SINGLE kernel node. Churn grid (R2-proven), one-shot TMA per CTA.
// Epilogue: ONE fire-and-forget u64 RED per CTA, packing
//   bits[44:64) = CTA count, bits[0:44) = fixed-point(2^18) partial sum.
// Completion: CTA GRID-1 (scheduled last) polls g_acc with relaxed loads,
// then writes *out and resets g_acc. No fences, no returning atomics
// (returning ATOMG cost R7 ~2us; gpu-scope fences cost R5/R6 ~8-10us).

#define S_DIM 56
#define N_IMG 128
#define B_BOX 5
#define C_CLS 20
#define CVEC  25                       // C+5
#define CELLS (N_IMG * S_DIM * S_DIM)  // 401408
#define TILE_CELLS 112                 // cells per block (67.2KB -> 3 CTAs/SM)
#define CPB   128                      // threads per block (16 idle in compute)
#define GRID  (CELLS / TILE_CELLS)     // 3584 (exact)
#define PW    (TILE_CELLS * CVEC * B_BOX)  // 14000 floats
#define TW    (TILE_CELLS * CVEC)          //  2800 floats
#define PBYTES (PW * 4)                // 56000 B (16B-multiple)
#define TBYTES (TW * 4)                // 11200 B (16B-multiple)
#define SMEM_BYTES (PBYTES + TBYTES)   // 67200 B dynamic smem

#define FIX_SCALE 262144.0             // 2^18
#define CNT_SHIFT 44
#define SUM_MASK  ((1ULL << CNT_SHIFT) - 1ULL)

__device__ unsigned long long g_acc = 0ULL;

__device__ __forceinline__ float sigmoid_f(float x) {
    // sigmoid(x) = 0.5 * tanh(0.5x) + 0.5  (1 MUFU)
    float t;
    asm("tanh.approx.f32 %0, %1;" : "=f"(t) : "f"(x * 0.5f));
    return fmaf(0.5f, t, 0.5f);
}

__device__ __forceinline__ uint32_t smem_u32(const void* p) {
    return (uint32_t)__cvta_generic_to_shared(p);
}

__global__ __launch_bounds__(CPB) void yolo_loss_kernel(
    const float* __restrict__ gp,   // predicts
    const float* __restrict__ gt,   // targets
    const float* __restrict__ ga,   // anchors (10 floats)
    float* __restrict__ out)
{
    extern __shared__ __align__(128) float sm[];
    float* sp = sm;        // [PW] predicts for this block's cells
    float* st = sm + PW;   // [TW] targets  for this block's cells
    __shared__ __align__(8) unsigned long long mbar;
    __shared__ float wsum[CPB / 32];

    const int tid = threadIdx.x;
    const uint32_t mbar_a = smem_u32(&mbar);

    if (tid == 0) {
        asm volatile("mbarrier.init.shared.b64 [%0], 1;" :: "r"(mbar_a) : "memory");
    }
    __syncthreads();

    // ---- One-shot TMA bulk copy of the whole tile ----
    if (tid == 0) {
        asm volatile("mbarrier.arrive.expect_tx.shared.b64 _, [%0], %1;"
                     :: "r"(mbar_a), "r"((uint32_t)SMEM_BYTES) : "memory");
        const char* gpp = (const char*)(gp + (size_t)blockIdx.x * PW);
        const char* gtp = (const char*)(gt + (size_t)blockIdx.x * TW);
        asm volatile(
            "cp.async.bulk.shared::cta.global.mbarrier::complete_tx::bytes [%0], [%1], %2, [%3];"
            :: "r"(smem_u32(sp)), "l"(gpp), "r"((uint32_t)PBYTES), "r"(mbar_a) : "memory");
        asm volatile(
            "cp.async.bulk.shared::cta.global.mbarrier::complete_tx::bytes [%0], [%1], %2, [%3];"
            :: "r"(smem_u32(st)), "l"(gtp), "r"((uint32_t)TBYTES), "r"(mbar_a) : "memory");
    }

    // ---- Wait for the bulk copy (acquire orders subsequent ld.shared) ----
    {
        uint32_t done;
        asm volatile(
            "{\n\t.reg .pred p;\n\t"
            "mbarrier.try_wait.parity.acquire.cta.shared::cta.b64 p, [%1], 0;\n\t"
            "selp.b32 %0, 1, 0, p;\n\t}"
            : "=r"(done) : "r"(mbar_a) : "memory");
        if (!done) {
            asm volatile(
                "{\n\t.reg .pred P1;\n\t"
                "WAIT_LOOP_%=:\n\t"
                "mbarrier.try_wait.parity.acquire.cta.shared::cta.b64 P1, [%0], 0, 0x989680;\n\t"
                "@P1 bra.uni WAIT_DONE_%=;\n\t"
                "bra.uni WAIT_LOOP_%=;\n\t"
                "WAIT_DONE_%=:\n\t}"
                :: "r"(mbar_a) : "memory");
        }
    }

    float loss = 0.0f;

    if (tid < TILE_CELLS) {
        // ---- Per-cell compute. smem strides 125 / 25 words: odd -> conflict-free ----
        const float* pc = sp + tid * (CVEC * B_BOX);
        const float* tc = st + tid * CVEC;

        const float e   = tc[C_CLS];
        const float tcx = tc[C_CLS + 1], tcy = tc[C_CLS + 2];
        const float tw  = tc[C_CLS + 3], th  = tc[C_CLS + 4];
        const float tx1 = tcx - 0.5f * tw, ty1 = tcy - 0.5f * th;
        const float tx2 = tcx + 0.5f * tw, ty2 = tcy + 0.5f * th;
        const float area_t = tw * th;

        // Argmax over IoU via cross-multiplication (dens > 0); init -> b=0 wins first.
        float bnum = -1.0f, bden = 1.0f;
        int   bidx = 0;
        float bsx = 0.f, bsy = 0.f, bw = 0.f, bh = 0.f;

#pragma unroll
        for (int b = 0; b < B_BOX; ++b) {
            const float* pb = pc + b * CVEC;
            const float sx = sigmoid_f(pb[C_CLS + 1]);
            const float sy = sigmoid_f(pb[C_CLS + 2]);
            const float w  = __expf(pb[C_CLS + 3]) * __ldg(ga + 2 * b);
            const float h  = __expf(pb[C_CLS + 4]) * __ldg(ga + 2 * b + 1);

            const float x1 = sx - 0.5f * w, y1 = sy - 0.5f * h;
            const float x2 = sx + 0.5f * w, y2 = sy + 0.5f * h;
            const float lx = fmaxf(x1, tx1), ly = fmaxf(y1, ty1);
            const float rx = fminf(x2, tx2), ry = fminf(y2, ty2);
            const float wi = fmaxf(rx - lx, 0.0f);
            const float hi = fmaxf(ry - ly, 0.0f);
            const float inter = wi * hi;
            const float den   = fmaf(w, h, area_t) - inter;

            // iou_b > iou_best  <=>  inter*bden > bnum*den  (strict > == first-max)
            if (inter * bden > bnum * den) {
                bidx = b; bnum = inter; bden = den;
                bsx = sx; bsy = sy; bw = w; bh = h;
            }
        }

        const float e2 = e * e;

        // loss_xcyc
        const float dx = bsx - tcx, dy = bsy - tcy;
        loss = e2 * (dx * dx + dy * dy);

        // loss_wh: sign(w)*sqrt(|w|+1e-6)
        const float pw = (bw > 0.f) ? sqrtf(bw + 1e-6f)
                                    : ((bw < 0.f) ? -sqrtf(-bw + 1e-6f) : 0.f);
        const float ph = (bh > 0.f) ? sqrtf(bh + 1e-6f)
                                    : ((bh < 0.f) ? -sqrtf(-bh + 1e-6f) : 0.f);
        const float dw = pw - tw, dh = ph - th;
        loss += e2 * (dw * dw + dh * dh);

        // loss_cls (class 0 of best box scaled by best_idx)
        const float* pbest = pc + bidx * CVEC;
        const float fbidx = (float)bidx;
        float cls = 0.0f;
#pragma unroll
        for (int c = 0; c < C_CLS; ++c) {
            float pv = pbest[c];
            if (c == 0) pv *= fbidx;
            const float d = pv - tc[c];
            cls = fmaf(d, d, cls);
        }
        loss += e2 * cls;

        // loss_obj + loss_noobj: [e^2 + (1-e)^2] * (pobj - e)^2
        const float dobj   = pbest[C_CLS] - e;
        const float one_me = 1.0f - e;
        loss += (e2 + one_me * one_me) * dobj * dobj;
    }

    // ---- Reduction: warp shuffle -> block ----
#pragma unroll
    for (int o = 16; o; o >>= 1)
        loss += __shfl_xor_sync(0xffffffffu, loss, o);

    if ((tid & 31) == 0) wsum[tid >> 5] = loss;
    __syncthreads();

    if (tid == 0) {
        float s = 0.0f;
#pragma unroll
        for (int i = 0; i < CPB / 32; ++i) s += wsum[i];

        // ONE fire-and-forget u64 RED: count in high bits, fixed-point sum low.
        const unsigned long long fx =
            (unsigned long long)__double2ll_rn((double)s * FIX_SCALE);
        const unsigned long long contrib = fx + (1ULL << CNT_SHIFT);
        asm volatile("red.relaxed.gpu.global.add.u64 [%0], %1;"
                     :: "l"(&g_acc), "l"(contrib) : "memory");

        // CTA GRID-1 (launched last by the churn scheduler) is the spinner:
        // poll until all GRID contributions (incl. our own) have applied.
        if (blockIdx.x == GRID - 1) {
            unsigned long long cur;
            for (;;) {
                asm volatile("ld.relaxed.gpu.global.u64 %0, [%1];"
                             : "=l"(cur) : "l"(&g_acc) : "memory");
                if ((cur >> CNT_SHIFT) == (unsigned long long)GRID) break;
                __nanosleep(128);
            }
            *out = (float)((double)(cur & SUM_MASK) * (1.0 / FIX_SCALE));
            // Reset for next replay: same-address ordering after our load;
            // kernel boundary orders it for the next graph replay.
            asm volatile("st.relaxed.gpu.global.u64 [%0], %1;"
                         :: "l"(&g_acc), "l"(0ULL) : "memory");
        }
    }
}

extern "C" void kernel_launch(void* const* d_in, const int* in_sizes, int n_in,
                              void* d_out, int out_size)
{
    const float* p = (const float*)d_in[0];
    const float* t = (const float*)d_in[1];
    const float* a = (const float*)d_in[2];
    float* out = (float*)d_out;

    cudaFuncSetAttribute(yolo_loss_kernel,
                         cudaFuncAttributeMaxDynamicSharedMemorySize, SMEM_BYTES);

    yolo_loss_kernel<<<GRID, CPB, SMEM_BYTES>>>(p, t, a, out);
}